// round 11
// baseline (speedup 1.0000x reference)
#include <cuda_runtime.h>

#define B_  64
#define J_  512
#define P_  768
#define NC_ 16
#define DC_ 64
#define WN_ 1024   // NC_*DC_

typedef unsigned long long ull;

// ---------------- scratch (device globals; no allocation allowed) ----------------
__device__ float  g_xbar[4][B_ * P_];       // colsum partials [jsplit][b*P+p]
__device__ float  g_o[B_ * WN_];            // routed outputs  [b][i*64+k]
__device__ float2 g_v2[B_][P_][16];         // v duplicated    [b][p][i]=(v,v)
__device__ float  g_yp[16][B_ * NC_ * P_];  // y partials      [jsplit][b][i][p]

// ---------------- packed f32x2 helpers ----------------
__device__ __forceinline__ ull ffma2(ull a, ull b, ull c) {
    ull d;
    asm("fma.rn.f32x2 %0, %1, %2, %3;" : "=l"(d) : "l"(a), "l"(b), "l"(c));
    return d;
}
__device__ __forceinline__ ull pack2(float v) {
    ull d; unsigned int u = __float_as_uint(v);
    asm("mov.b64 %0, {%1, %1};" : "=l"(d) : "r"(u));
    return d;
}
__device__ __forceinline__ float2 unpack2(ull u) {
    float2 f;
    f.x = __uint_as_float((unsigned int)u);
    f.y = __uint_as_float((unsigned int)(u >> 32));
    return f;
}

// ---------------- K1: xbar partials (float4, 16 lines in flight) --------------
__global__ void __launch_bounds__(192) k_colsum(const float* __restrict__ x) {
    int pq = threadIdx.x;
    int js = blockIdx.x;
    int b  = blockIdx.y;
    const float4* xp = (const float4*)(x + ((size_t)b * J_ + (size_t)js * 128) * P_) + pq;
    float4 a0 = make_float4(0.f, 0.f, 0.f, 0.f), a1 = a0, a2 = a0, a3 = a0;
    #pragma unroll 8
    for (int j = 0; j < 128; j += 4) {
        float4 v0 = xp[(size_t)(j + 0) * 192];
        float4 v1 = xp[(size_t)(j + 1) * 192];
        float4 v2 = xp[(size_t)(j + 2) * 192];
        float4 v3 = xp[(size_t)(j + 3) * 192];
        a0.x += v0.x; a0.y += v0.y; a0.z += v0.z; a0.w += v0.w;
        a1.x += v1.x; a1.y += v1.y; a1.z += v1.z; a1.w += v1.w;
        a2.x += v2.x; a2.y += v2.y; a2.z += v2.z; a2.w += v2.w;
        a3.x += v3.x; a3.y += v3.y; a3.z += v3.z; a3.w += v3.w;
    }
    float4 s;
    s.x = (a0.x + a1.x) + (a2.x + a3.x);
    s.y = (a0.y + a1.y) + (a2.y + a3.y);
    s.z = (a0.z + a1.z) + (a2.z + a3.z);
    s.w = (a0.w + a1.w) + (a2.w + a3.w);
    *(float4*)(g_xbar[js] + b * P_ + 4 * pq) = s;
}

// ---------------- K2: s = src @ W_i, squash -> g_o (and out at final) ---------
template <int MODE>
__global__ void __launch_bounds__(512) k_s(const float* __restrict__ W,
                                           float* __restrict__ out) {
    int i  = blockIdx.x;
    int b0 = blockIdx.y * 4;
    __shared__ float  ys[4][P_];
    __shared__ float2 ss[4][4][32];
    for (int idx = threadIdx.x; idx < 4 * (P_ / 4); idx += 512) {
        int bb = idx / (P_ / 4), pq = idx - bb * (P_ / 4);
        float4 s;
        if (MODE == 0) {
            size_t off = (size_t)(b0 + bb) * P_;
            float4 v0 = ((const float4*)(g_xbar[0] + off))[pq];
            float4 v1 = ((const float4*)(g_xbar[1] + off))[pq];
            float4 v2 = ((const float4*)(g_xbar[2] + off))[pq];
            float4 v3 = ((const float4*)(g_xbar[3] + off))[pq];
            s.x = (v0.x + v1.x) + (v2.x + v3.x);
            s.y = (v0.y + v1.y) + (v2.y + v3.y);
            s.z = (v0.z + v1.z) + (v2.z + v3.z);
            s.w = (v0.w + v1.w) + (v2.w + v3.w);
        } else {
            size_t off = ((size_t)(b0 + bb) * NC_ + i) * P_;
            s = make_float4(0.f, 0.f, 0.f, 0.f);
            #pragma unroll
            for (int sp = 0; sp < 16; sp++) {
                float4 v = ((const float4*)(g_yp[sp] + off))[pq];
                s.x += v.x; s.y += v.y; s.z += v.z; s.w += v.w;
            }
        }
        ((float4*)ys[bb])[pq] = s;
    }
    __syncthreads();

    int w = threadIdx.x >> 5, l = threadIdx.x & 31;
    int bb = w & 3, ph = w >> 2;
    const float* yrow = ys[bb] + ph * 192;
    const float* wrow = W + ((size_t)ph * 192) * WN_ + i * DC_ + 2 * l;

    float2 a[8];
    #pragma unroll
    for (int u = 0; u < 8; u++) a[u] = make_float2(0.f, 0.f);
    for (int p = 0; p < 192; p += 8) {
        #pragma unroll
        for (int u = 0; u < 8; u++) {
            float2 wv = *(const float2*)(wrow + (size_t)(p + u) * WN_);
            float yv = yrow[p + u];
            a[u].x += wv.x * yv; a[u].y += wv.y * yv;
        }
    }
    float2 acc;
    acc.x = ((a[0].x + a[1].x) + (a[2].x + a[3].x)) + ((a[4].x + a[5].x) + (a[6].x + a[7].x));
    acc.y = ((a[0].y + a[1].y) + (a[2].y + a[3].y)) + ((a[4].y + a[5].y) + (a[6].y + a[7].y));
    ss[ph][bb][l] = acc;
    __syncthreads();

    if (w < 4) {
        float2 p0 = ss[0][w][l], p1 = ss[1][w][l], p2 = ss[2][w][l], p3 = ss[3][w][l];
        float2 s2 = make_float2((p0.x + p1.x) + (p2.x + p3.x),
                                (p0.y + p1.y) + (p2.y + p3.y));
        if (MODE == 0) { s2.x *= 0.0625f; s2.y *= 0.0625f; }
        float sq = s2.x * s2.x + s2.y * s2.y;
        #pragma unroll
        for (int s = 16; s > 0; s >>= 1) sq += __shfl_xor_sync(0xffffffffu, sq, s);
        float r = rsqrtf(sq + 1e-7f);
        s2.x *= r; s2.y *= r;
        size_t ob = ((size_t)(b0 + w) * NC_ + i) * DC_ + 2 * l;
        *(float2*)(g_o + ob) = s2;
        if (out) *(float2*)(out + ob) = s2;
    }
}

// ---------------- K3: v2[b][p][i] = (W[p,i*64:].o[b,i,:]) duplicated ----------
__global__ void __launch_bounds__(128) k_v(const float* __restrict__ W) {
    int pc = blockIdx.x * 16;
    int bg = blockIdx.y * 4;
    __shared__ float4 ws[16 * 256];   // 64KB, swizzled
    __shared__ float4 os[4][256];
    int t = threadIdx.x;

    for (int idx = t; idx < 4 * 256; idx += 128) {
        int bb = idx >> 8, q = idx & 255;
        os[bb][q] = ((const float4*)(g_o + (size_t)(bg + bb) * WN_))[q];
    }
    for (int idx = t; idx < 16 * 256; idx += 128) {
        int p = idx >> 8, q = idx & 255;
        float4 wv = ((const float4*)(W + (size_t)(pc + p) * WN_))[q];
        int qs = (q & ~15) | ((q & 15) ^ p);
        ws[p * 256 + qs] = wv;
    }
    __syncthreads();

    int p = t & 15, ip = t >> 4;
    float ax[4] = {0.f, 0.f, 0.f, 0.f};
    float ay[4] = {0.f, 0.f, 0.f, 0.f};
    #pragma unroll
    for (int qq = 0; qq < 32; qq++) {
        int q  = ip * 32 + qq;
        int qs = (q & ~15) | ((q & 15) ^ p);
        float4 wv = ws[p * 256 + qs];
        #pragma unroll
        for (int bb = 0; bb < 4; bb++) {
            float4 ov = os[bb][q];
            float d = wv.x * ov.x + wv.y * ov.y + wv.z * ov.z + wv.w * ov.w;
            if (qq < 16) ax[bb] += d; else ay[bb] += d;
        }
    }
    #pragma unroll
    for (int bb = 0; bb < 4; bb++) {
        g_v2[bg + bb][pc + p][2 * ip]     = make_float2(ax[bb], ax[bb]);
        g_v2[bg + bb][pc + p][2 * ip + 1] = make_float2(ay[bb], ay[bb]);
    }
}

// ---------------- K4: fused route + softmax + y, j-tile 32, occ-3 -------------
// xs: [k=128][8 units of 16B], unit col = jq ^ ((k>>2)&7)  (16KB)
// vt2: [k=128][16 f32x2 dup]                               (16KB)
// pblw[8][32][17] overlays xs+vt after route. cs[32][4] float4 at +32768.
#define RY_SMEM (32768 + 2048)

__global__ void __launch_bounds__(256, 3) k_routey(const float* __restrict__ x) {
    extern __shared__ char sm[];
    float*      xsf  = (float*)sm;
    ulonglong2* xs16 = (ulonglong2*)sm;
    float2*     vt2  = (float2*)(sm + 16384);
    uint4*      vt2u = (uint4*)(sm + 16384);
    float*      pblw = (float*)sm;                    // [8][32][17] overlay
    float4*     cs   = (float4*)(sm + 32768);         // [32][4]

    int b  = blockIdx.y;
    int jc = blockIdx.x;                              // 0..15
    const float* xb = x + ((size_t)b * J_ + jc * 32) * P_;
    int t = threadIdx.x, w = t >> 5, l = t & 31;
    int tj = l & 3, ti = l >> 2;                      // j-octet 8tj.., ipair ti

    ull acc[8];
    #pragma unroll
    for (int q = 0; q < 8; q++) acc[q] = 0ull;

    const uint4* v2src = (const uint4*)&g_v2[b][0][0];   // 8 units per p-row

    // staging coords: thread (q,w,l): j = 4w + (l&3), kq = q*8 + (l>>2)
    int sjr = l & 3, skql = l >> 2;
    int sj  = 4 * w + sjr;

    // prologue: full prefetch of slab 0
    float4 rx[4];
    uint4  rv[4];
    #pragma unroll
    for (int q = 0; q < 4; q++)
        rx[q] = ((const float4*)(xb + (size_t)sj * P_))[q * 8 + skql];
    #pragma unroll
    for (int q = 0; q < 4; q++)
        rv[q] = v2src[t + 256 * q];

    for (int s = 0; s < 6; s++) {
        __syncthreads();
        // xs transpose store (conflict-free: 8 cols x 4 jr = 32 banks)
        #pragma unroll
        for (int q = 0; q < 4; q++) {
            int kq  = q * 8 + skql;
            int col = w ^ (kq & 7);
            int base = (4 * kq) * 32 + col * 4 + sjr;
            xsf[base +  0] = rx[q].x;
            xsf[base + 32] = rx[q].y;
            xsf[base + 64] = rx[q].z;
            xsf[base + 96] = rx[q].w;
        }
        #pragma unroll
        for (int q = 0; q < 4; q++)
            vt2u[t + 256 * q] = rv[q];
        __syncthreads();
        // prefetch next slab during compute
        if (s < 5) {
            #pragma unroll
            for (int q = 0; q < 4; q++)
                rx[q] = ((const float4*)(xb + (size_t)sj * P_ + 128 * (s + 1)))[q * 8 + skql];
            #pragma unroll
            for (int q = 0; q < 4; q++)
                rv[q] = v2src[(size_t)(s + 1) * 1024 + t + 256 * q];
        }
        // compute: warp's k sub-range [16w, 16w+16)
        #pragma unroll
        for (int kk = 0; kk < 16; kk++) {
            int k  = 16 * w + kk;
            int sw = (k >> 2) & 7;
            ulonglong2 xp0 = xs16[k * 8 + ((2 * tj)     ^ sw)];   // j 8tj..+3
            ulonglong2 xp1 = xs16[k * 8 + ((2 * tj + 1) ^ sw)];   // j 8tj+4..+7
            ulonglong2 vv  = *(const ulonglong2*)&vt2[k * 16 + 2 * ti];
            acc[0] = ffma2(xp0.x, vv.x, acc[0]);
            acc[1] = ffma2(xp0.x, vv.y, acc[1]);
            acc[2] = ffma2(xp0.y, vv.x, acc[2]);
            acc[3] = ffma2(xp0.y, vv.y, acc[3]);
            acc[4] = ffma2(xp1.x, vv.x, acc[4]);
            acc[5] = ffma2(xp1.x, vv.y, acc[5]);
            acc[6] = ffma2(xp1.y, vv.x, acc[6]);
            acc[7] = ffma2(xp1.y, vv.y, acc[7]);
        }
    }
    __syncthreads();   // xs/vt dead; region becomes pblw
    // per-warp partial logits: thread covers j 8tj..8tj+7, i {2ti, 2ti+1}
    #pragma unroll
    for (int jp = 0; jp < 4; jp++) {
        int j0 = 8 * tj + 2 * jp;
        #pragma unroll
        for (int ii = 0; ii < 2; ii++) {
            float2 f = unpack2(acc[2 * jp + ii]);
            pblw[w * 544 + j0 * 17 + 2 * ti + ii]       = f.x;
            pblw[w * 544 + (j0 + 1) * 17 + 2 * ti + ii] = f.y;
        }
    }
    __syncthreads();
    if (t < 32) {
        float bl[16];
        #pragma unroll
        for (int q = 0; q < 16; q++) {
            float s = 0.f;
            #pragma unroll
            for (int ww = 0; ww < 8; ww++) s += pblw[ww * 544 + t * 17 + q];
            bl[q] = s;
        }
        float m = bl[0];
        #pragma unroll
        for (int q = 1; q < 16; q++) m = fmaxf(m, bl[q]);
        float sum = 0.f;
        #pragma unroll
        for (int q = 0; q < 16; q++) { bl[q] = __expf(bl[q] - m); sum += bl[q]; }
        float inv = 1.0f / sum;
        #pragma unroll
        for (int q = 0; q < 4; q++)
            cs[t * 4 + q] = make_float4(bl[4 * q] * inv, bl[4 * q + 1] * inv,
                                        bl[4 * q + 2] * inv, bl[4 * q + 3] * inv);
    }
    __syncthreads();

    // ---- y phase, pass A: p columns {t, t+256}, all 16 i ----
    {
        ull ya[16];
        #pragma unroll
        for (int q = 0; q < 16; q++) ya[q] = 0ull;
        #pragma unroll 2
        for (int j = 0; j < 32; j++) {
            float a0 = xb[(size_t)j * P_ + t];
            float a1 = xb[(size_t)j * P_ + t + 256];
            ull x0 = pack2(a0), x1 = pack2(a1);
            const ulonglong2* crow = (const ulonglong2*)(cs + j * 4);
            #pragma unroll
            for (int q = 0; q < 4; q++) {
                ulonglong2 c = crow[q];
                ya[2 * q]         = ffma2(x0, c.x, ya[2 * q]);
                ya[2 * q + 1]     = ffma2(x0, c.y, ya[2 * q + 1]);
                ya[8 + 2 * q]     = ffma2(x1, c.x, ya[8 + 2 * q]);
                ya[8 + 2 * q + 1] = ffma2(x1, c.y, ya[8 + 2 * q + 1]);
            }
        }
        #pragma unroll
        for (int ip = 0; ip < 8; ip++) {
            float2 f0 = unpack2(ya[ip]);
            float2 f1 = unpack2(ya[8 + ip]);
            g_yp[jc][((size_t)b * NC_ + 2 * ip)     * P_ + t]       = f0.x;
            g_yp[jc][((size_t)b * NC_ + 2 * ip + 1) * P_ + t]       = f0.y;
            g_yp[jc][((size_t)b * NC_ + 2 * ip)     * P_ + t + 256] = f1.x;
            g_yp[jc][((size_t)b * NC_ + 2 * ip + 1) * P_ + t + 256] = f1.y;
        }
    }
    // ---- y phase, pass B: p column {t+512} ----
    {
        ull yb[8];
        #pragma unroll
        for (int q = 0; q < 8; q++) yb[q] = 0ull;
        #pragma unroll 2
        for (int j = 0; j < 32; j++) {
            float a2 = xb[(size_t)j * P_ + t + 512];
            ull x2 = pack2(a2);
            const ulonglong2* crow = (const ulonglong2*)(cs + j * 4);
            #pragma unroll
            for (int q = 0; q < 4; q++) {
                ulonglong2 c = crow[q];
                yb[2 * q]     = ffma2(x2, c.x, yb[2 * q]);
                yb[2 * q + 1] = ffma2(x2, c.y, yb[2 * q + 1]);
            }
        }
        #pragma unroll
        for (int ip = 0; ip < 8; ip++) {
            float2 f = unpack2(yb[ip]);
            g_yp[jc][((size_t)b * NC_ + 2 * ip)     * P_ + t + 512] = f.x;
            g_yp[jc][((size_t)b * NC_ + 2 * ip + 1) * P_ + t + 512] = f.y;
        }
    }
}

// ---------------- launch ----------------
extern "C" void kernel_launch(void* const* d_in, const int* in_sizes, int n_in,
                              void* d_out, int out_size) {
    const float* x = (const float*)d_in[0];
    const float* W = (const float*)d_in[1];
    if (n_in >= 2 && in_sizes[0] < in_sizes[1]) {
        const float* tmp = x; x = W; W = tmp;
    }
    float* out = (float*)d_out;
    (void)out_size;

    cudaFuncSetAttribute(k_routey, cudaFuncAttributeMaxDynamicSharedMemorySize,
                         RY_SMEM);

    dim3 gsq(16, 16);

    k_colsum<<<dim3(4, 64), 192>>>(x);
    k_s<0><<<gsq, 512>>>(W, nullptr);
    k_v<<<dim3(48, 16), 128>>>(W);

    // iteration 1
    k_routey<<<dim3(16, 64), 256, RY_SMEM>>>(x);
    k_s<1><<<gsq, 512>>>(W, nullptr);
    k_v<<<dim3(48, 16), 128>>>(W);

    // iteration 2 (final)
    k_routey<<<dim3(16, 64), 256, RY_SMEM>>>(x);
    k_s<1><<<gsq, 512>>>(W, out);
}

// round 12
// speedup vs baseline: 1.0896x; 1.0896x over previous
#include <cuda_runtime.h>

#define B_  64
#define J_  512
#define P_  768
#define NC_ 16
#define DC_ 64
#define WN_ 1024   // NC_*DC_

typedef unsigned long long ull;

// ---------------- scratch (device globals; no allocation allowed) ----------------
__device__ float  g_xbar[4][B_ * P_];       // colsum partials [jsplit][b*P+p]
__device__ float  g_o[B_ * WN_];            // routed outputs  [b][i*64+k]
__device__ float2 g_v2[B_][P_][16];         // v duplicated    [b][p][i]=(v,v)
__device__ float  g_yp[8][B_ * NC_ * P_];   // y partials      [jsplit][b][i][p]

// ---------------- packed f32x2 helpers ----------------
__device__ __forceinline__ ull ffma2(ull a, ull b, ull c) {
    ull d;
    asm("fma.rn.f32x2 %0, %1, %2, %3;" : "=l"(d) : "l"(a), "l"(b), "l"(c));
    return d;
}
__device__ __forceinline__ ull pack2(float v) {
    ull d; unsigned int u = __float_as_uint(v);
    asm("mov.b64 %0, {%1, %1};" : "=l"(d) : "r"(u));
    return d;
}
__device__ __forceinline__ float2 unpack2(ull u) {
    float2 f;
    f.x = __uint_as_float((unsigned int)u);
    f.y = __uint_as_float((unsigned int)(u >> 32));
    return f;
}

// ---------------- K1: xbar partials (float4, 16 lines in flight) --------------
__global__ void __launch_bounds__(192) k_colsum(const float* __restrict__ x) {
    int pq = threadIdx.x;
    int js = blockIdx.x;
    int b  = blockIdx.y;
    const float4* xp = (const float4*)(x + ((size_t)b * J_ + (size_t)js * 128) * P_) + pq;
    float4 a0 = make_float4(0.f, 0.f, 0.f, 0.f), a1 = a0, a2 = a0, a3 = a0;
    #pragma unroll 8
    for (int j = 0; j < 128; j += 4) {
        float4 v0 = xp[(size_t)(j + 0) * 192];
        float4 v1 = xp[(size_t)(j + 1) * 192];
        float4 v2 = xp[(size_t)(j + 2) * 192];
        float4 v3 = xp[(size_t)(j + 3) * 192];
        a0.x += v0.x; a0.y += v0.y; a0.z += v0.z; a0.w += v0.w;
        a1.x += v1.x; a1.y += v1.y; a1.z += v1.z; a1.w += v1.w;
        a2.x += v2.x; a2.y += v2.y; a2.z += v2.z; a2.w += v2.w;
        a3.x += v3.x; a3.y += v3.y; a3.z += v3.z; a3.w += v3.w;
    }
    float4 s;
    s.x = (a0.x + a1.x) + (a2.x + a3.x);
    s.y = (a0.y + a1.y) + (a2.y + a3.y);
    s.z = (a0.z + a1.z) + (a2.z + a3.z);
    s.w = (a0.w + a1.w) + (a2.w + a3.w);
    *(float4*)(g_xbar[js] + b * P_ + 4 * pq) = s;
}

// ---------------- K2: s = src @ W_i, squash -> g_o (and out at final) ---------
// grid (i=16, bg=16), block 512 = 16 warps: warp -> (b = w&3, pquarter = w>>2).
// Lane (qk=l&15, pofs=l>>4): float4 W loads, 2 rows/warp-instr, 8 indep accs.
template <int MODE>
__global__ void __launch_bounds__(512) k_s(const float* __restrict__ W,
                                           float* __restrict__ out) {
    int i  = blockIdx.x;
    int b0 = blockIdx.y * 4;
    __shared__ float  ys[4][P_];
    __shared__ float4 ss[4][4][16];
    for (int idx = threadIdx.x; idx < 4 * (P_ / 4); idx += 512) {
        int bb = idx / (P_ / 4), pq = idx - bb * (P_ / 4);
        float4 s;
        if (MODE == 0) {
            size_t off = (size_t)(b0 + bb) * P_;
            float4 v0 = ((const float4*)(g_xbar[0] + off))[pq];
            float4 v1 = ((const float4*)(g_xbar[1] + off))[pq];
            float4 v2 = ((const float4*)(g_xbar[2] + off))[pq];
            float4 v3 = ((const float4*)(g_xbar[3] + off))[pq];
            s.x = (v0.x + v1.x) + (v2.x + v3.x);
            s.y = (v0.y + v1.y) + (v2.y + v3.y);
            s.z = (v0.z + v1.z) + (v2.z + v3.z);
            s.w = (v0.w + v1.w) + (v2.w + v3.w);
        } else {
            size_t off = ((size_t)(b0 + bb) * NC_ + i) * P_;
            s = make_float4(0.f, 0.f, 0.f, 0.f);
            #pragma unroll
            for (int sp = 0; sp < 8; sp++) {
                float4 v = ((const float4*)(g_yp[sp] + off))[pq];
                s.x += v.x; s.y += v.y; s.z += v.z; s.w += v.w;
            }
        }
        ((float4*)ys[bb])[pq] = s;
    }
    __syncthreads();

    int w = threadIdx.x >> 5, l = threadIdx.x & 31;
    int bb = w & 3, ph = w >> 2;                 // p-quarter of 192
    int qk = l & 15, pofs = l >> 4;
    const float* yrow  = ys[bb] + ph * 192;
    const float* wbase = W + ((size_t)(ph * 192)) * WN_ + i * DC_ + 4 * qk;

    float4 a[8];
    #pragma unroll
    for (int u = 0; u < 8; u++) a[u] = make_float4(0.f, 0.f, 0.f, 0.f);
    for (int p0 = 0; p0 < 192; p0 += 16) {
        #pragma unroll
        for (int u = 0; u < 8; u++) {
            int pr = p0 + 2 * u + pofs;
            float4 wv = *(const float4*)(wbase + (size_t)pr * WN_);
            float yv = yrow[pr];
            a[u].x += wv.x * yv; a[u].y += wv.y * yv;
            a[u].z += wv.z * yv; a[u].w += wv.w * yv;
        }
    }
    float4 acc;
    acc.x = ((a[0].x + a[1].x) + (a[2].x + a[3].x)) + ((a[4].x + a[5].x) + (a[6].x + a[7].x));
    acc.y = ((a[0].y + a[1].y) + (a[2].y + a[3].y)) + ((a[4].y + a[5].y) + (a[6].y + a[7].y));
    acc.z = ((a[0].z + a[1].z) + (a[2].z + a[3].z)) + ((a[4].z + a[5].z) + (a[6].z + a[7].z));
    acc.w = ((a[0].w + a[1].w) + (a[2].w + a[3].w)) + ((a[4].w + a[5].w) + (a[6].w + a[7].w));
    // combine the two p-parity halves (lanes l and l^16 share qk)
    acc.x += __shfl_xor_sync(0xffffffffu, acc.x, 16);
    acc.y += __shfl_xor_sync(0xffffffffu, acc.y, 16);
    acc.z += __shfl_xor_sync(0xffffffffu, acc.z, 16);
    acc.w += __shfl_xor_sync(0xffffffffu, acc.w, 16);
    if (pofs == 0) ss[ph][bb][qk] = acc;
    __syncthreads();

    if (w < 4) {
        int qk2 = l >> 1, hi = l & 1;
        float2 s2 = make_float2(0.f, 0.f);
        #pragma unroll
        for (int p2 = 0; p2 < 4; p2++) {
            float4 v = ss[p2][w][qk2];
            s2.x += hi ? v.z : v.x;
            s2.y += hi ? v.w : v.y;
        }
        if (MODE == 0) { s2.x *= 0.0625f; s2.y *= 0.0625f; }
        float sq = s2.x * s2.x + s2.y * s2.y;
        #pragma unroll
        for (int s = 16; s > 0; s >>= 1) sq += __shfl_xor_sync(0xffffffffu, sq, s);
        float r = rsqrtf(sq + 1e-7f);
        s2.x *= r; s2.y *= r;
        size_t ob = ((size_t)(b0 + w) * NC_ + i) * DC_ + 2 * l;
        *(float2*)(g_o + ob) = s2;
        if (out) *(float2*)(out + ob) = s2;
    }
}

// ---------------- K3: v2[b][p][i] = (W[p,i*64:].o[b,i,:]) duplicated ----------
__global__ void __launch_bounds__(128) k_v(const float* __restrict__ W) {
    int pc = blockIdx.x * 16;
    int bg = blockIdx.y * 4;
    __shared__ float4 ws[16 * 256];   // 64KB, swizzled
    __shared__ float4 os[4][256];
    int t = threadIdx.x;

    for (int idx = t; idx < 4 * 256; idx += 128) {
        int bb = idx >> 8, q = idx & 255;
        os[bb][q] = ((const float4*)(g_o + (size_t)(bg + bb) * WN_))[q];
    }
    for (int idx = t; idx < 16 * 256; idx += 128) {
        int p = idx >> 8, q = idx & 255;
        float4 wv = ((const float4*)(W + (size_t)(pc + p) * WN_))[q];
        int qs = (q & ~15) | ((q & 15) ^ p);
        ws[p * 256 + qs] = wv;
    }
    __syncthreads();

    int p = t & 15, ip = t >> 4;
    float ax[4] = {0.f, 0.f, 0.f, 0.f};
    float ay[4] = {0.f, 0.f, 0.f, 0.f};
    #pragma unroll
    for (int qq = 0; qq < 32; qq++) {
        int q  = ip * 32 + qq;
        int qs = (q & ~15) | ((q & 15) ^ p);
        float4 wv = ws[p * 256 + qs];
        #pragma unroll
        for (int bb = 0; bb < 4; bb++) {
            float4 ov = os[bb][q];
            float d = wv.x * ov.x + wv.y * ov.y + wv.z * ov.z + wv.w * ov.w;
            if (qq < 16) ax[bb] += d; else ay[bb] += d;
        }
    }
    #pragma unroll
    for (int bb = 0; bb < 4; bb++) {
        g_v2[bg + bb][pc + p][2 * ip]     = make_float2(ax[bb], ax[bb]);
        g_v2[bg + bb][pc + p][2 * ip + 1] = make_float2(ay[bb], ay[bb]);
    }
}

// ---------------- K4: fused route (slab GEMM + softmax) + y partials ----------
// R10 config: full register prefetch + atomic-free merge + pipelined y phase.
#define RY_A    35072              // xs 32KB overlaid with pblw[8][64][17]
#define RY_VT   (128 * 16 * 8)     // 16384
#define RY_CS   (64 * 4 * 16)      //  4096
#define RY_SMEM (RY_A + RY_VT + RY_CS)

__global__ void __launch_bounds__(256, 2) k_routey(const float* __restrict__ x) {
    extern __shared__ char sm[];
    float*      xsf  = (float*)sm;                    // scalar view of xs units
    ulonglong2* xs16 = (ulonglong2*)sm;               // 16B-unit view
    float*      pblw = (float*)sm;                    // [8][64][17] overlay
    float2*     vt2  = (float2*)(sm + RY_A);          // [k][16]
    uint4*      vt2u = (uint4*)(sm + RY_A);
    float4*     cs   = (float4*)(sm + RY_A + RY_VT);  // [64][4]

    int b  = blockIdx.y;
    int jc = blockIdx.x;
    const float* xb = x + ((size_t)b * J_ + jc * 64) * P_;
    int t = threadIdx.x, w = t >> 5, l = t & 31;
    int tj = l & 7, ti = l >> 3;

    ull acc[16];
    #pragma unroll
    for (int q = 0; q < 16; q++) acc[q] = 0ull;

    const uint4* v2src = (const uint4*)&g_v2[b][0][0];   // 8 units per p-row

    // staging coordinates
    int sj[8], skq[8];
    #pragma unroll
    for (int q = 0; q < 8; q++) {
        int m = q * 8 + w;
        sj[q]  = (m & 15) * 4 + (l & 3);
        skq[q] = (m >> 4) * 8 + (l >> 2);
    }

    // prologue: FULL prefetch of slab 0 (x and v)
    float4 rx[8];
    uint4  rv[4];
    #pragma unroll
    for (int q = 0; q < 8; q++)
        rx[q] = ((const float4*)(xb + (size_t)sj[q] * P_))[skq[q]];
    #pragma unroll
    for (int q = 0; q < 4; q++)
        rv[q] = v2src[t + 256 * q];

    for (int s = 0; s < 6; s++) {
        __syncthreads();
        // xs transpose store (conflict-free via xor swizzle), pure STS
        #pragma unroll
        for (int q = 0; q < 8; q++) {
            int jq = sj[q] >> 2, jr = sj[q] & 3;
            int swz = jq ^ (skq[q] & 15);
            int base = (4 * skq[q]) * 16 + swz;
            xsf[(base + 0 * 16) * 4 + jr] = rx[q].x;
            xsf[(base + 1 * 16) * 4 + jr] = rx[q].y;
            xsf[(base + 2 * 16) * 4 + jr] = rx[q].z;
            xsf[(base + 3 * 16) * 4 + jr] = rx[q].w;
        }
        #pragma unroll
        for (int q = 0; q < 4; q++)
            vt2u[t + 256 * q] = rv[q];
        __syncthreads();
        // prefetch next slab during compute
        if (s < 5) {
            #pragma unroll
            for (int q = 0; q < 8; q++)
                rx[q] = ((const float4*)(xb + (size_t)sj[q] * P_ + 128 * (s + 1)))[skq[q]];
            #pragma unroll
            for (int q = 0; q < 4; q++)
                rv[q] = v2src[(size_t)(s + 1) * 1024 + t + 256 * q];
        }
        // compute: warp's k sub-range [16w, 16w+16)
        #pragma unroll
        for (int kk = 0; kk < 16; kk++) {
            int k = 16 * w + kk;
            int sw = (k >> 2) & 15;
            ulonglong2 xp0 = xs16[k * 16 + ((2 * tj)     ^ sw)];
            ulonglong2 xp1 = xs16[k * 16 + ((2 * tj + 1) ^ sw)];
            ulonglong2 v01 = *(const ulonglong2*)&vt2[k * 16 + 4 * ti];
            ulonglong2 v23 = *(const ulonglong2*)&vt2[k * 16 + 4 * ti + 2];
            acc[0]  = ffma2(xp0.x, v01.x, acc[0]);
            acc[1]  = ffma2(xp0.x, v01.y, acc[1]);
            acc[2]  = ffma2(xp0.x, v23.x, acc[2]);
            acc[3]  = ffma2(xp0.x, v23.y, acc[3]);
            acc[4]  = ffma2(xp0.y, v01.x, acc[4]);
            acc[5]  = ffma2(xp0.y, v01.y, acc[5]);
            acc[6]  = ffma2(xp0.y, v23.x, acc[6]);
            acc[7]  = ffma2(xp0.y, v23.y, acc[7]);
            acc[8]  = ffma2(xp1.x, v01.x, acc[8]);
            acc[9]  = ffma2(xp1.x, v01.y, acc[9]);
            acc[10] = ffma2(xp1.x, v23.x, acc[10]);
            acc[11] = ffma2(xp1.x, v23.y, acc[11]);
            acc[12] = ffma2(xp1.y, v01.x, acc[12]);
            acc[13] = ffma2(xp1.y, v01.y, acc[13]);
            acc[14] = ffma2(xp1.y, v23.x, acc[14]);
            acc[15] = ffma2(xp1.y, v23.y, acc[15]);
        }
    }
    __syncthreads();   // xs dead; region A becomes pblw
    // per-warp partial logits (plain STS, no atomics)
    #pragma unroll
    for (int jp = 0; jp < 4; jp++) {
        int j0 = 8 * tj + 2 * jp;
        #pragma unroll
        for (int ii = 0; ii < 4; ii++) {
            float2 f = unpack2(acc[4 * jp + ii]);
            pblw[w * 1088 + j0 * 17 + 4 * ti + ii]       = f.x;
            pblw[w * 1088 + (j0 + 1) * 17 + 4 * ti + ii] = f.y;
        }
    }
    __syncthreads();
    if (t < 64) {
        float bl[16];
        #pragma unroll
        for (int q = 0; q < 16; q++) {
            float s = 0.f;
            #pragma unroll
            for (int ww = 0; ww < 8; ww++) s += pblw[ww * 1088 + t * 17 + q];
            bl[q] = s;
        }
        float m = bl[0];
        #pragma unroll
        for (int q = 1; q < 16; q++) m = fmaxf(m, bl[q]);
        float sum = 0.f;
        #pragma unroll
        for (int q = 0; q < 16; q++) { bl[q] = __expf(bl[q] - m); sum += bl[q]; }
        float inv = 1.0f / sum;
        #pragma unroll
        for (int q = 0; q < 4; q++)
            cs[t * 4 + q] = make_float4(bl[4 * q] * inv, bl[4 * q + 1] * inv,
                                        bl[4 * q + 2] * inv, bl[4 * q + 3] * inv);
    }
    __syncthreads();

    // ---- y phase: software-pipelined (batch 4 j, prefetch next batch) ----
    ull ya[24];
    #pragma unroll
    for (int q = 0; q < 24; q++) ya[q] = 0ull;

    float c0[4], c1[4], c2[4];
    #pragma unroll
    for (int u = 0; u < 4; u++) {
        const float* xr = xb + (size_t)u * P_;
        c0[u] = xr[t]; c1[u] = xr[t + 256]; c2[u] = xr[t + 512];
    }
    for (int jb = 0; jb < 64; jb += 4) {
        float n0[4], n1[4], n2[4];
        if (jb < 60) {
            #pragma unroll
            for (int u = 0; u < 4; u++) {
                const float* xn = xb + (size_t)(jb + 4 + u) * P_;
                n0[u] = xn[t]; n1[u] = xn[t + 256]; n2[u] = xn[t + 512];
            }
        } else {
            #pragma unroll
            for (int u = 0; u < 4; u++) { n0[u] = 0.f; n1[u] = 0.f; n2[u] = 0.f; }
        }
        #pragma unroll
        for (int u = 0; u < 4; u++) {
            int j = jb + u;
            ull x0 = pack2(c0[u]), x1 = pack2(c1[u]), x2 = pack2(c2[u]);
            const ulonglong2* crow = (const ulonglong2*)(cs + j * 4);
            ulonglong2 ca = crow[0];
            ya[0]  = ffma2(x0, ca.x, ya[0]);  ya[8]  = ffma2(x1, ca.x, ya[8]);  ya[16] = ffma2(x2, ca.x, ya[16]);
            ya[1]  = ffma2(x0, ca.y, ya[1]);  ya[9]  = ffma2(x1, ca.y, ya[9]);  ya[17] = ffma2(x2, ca.y, ya[17]);
            ulonglong2 cb2 = crow[1];
            ya[2]  = ffma2(x0, cb2.x, ya[2]); ya[10] = ffma2(x1, cb2.x, ya[10]); ya[18] = ffma2(x2, cb2.x, ya[18]);
            ya[3]  = ffma2(x0, cb2.y, ya[3]); ya[11] = ffma2(x1, cb2.y, ya[11]); ya[19] = ffma2(x2, cb2.y, ya[19]);
            ulonglong2 cc = crow[2];
            ya[4]  = ffma2(x0, cc.x, ya[4]);  ya[12] = ffma2(x1, cc.x, ya[12]); ya[20] = ffma2(x2, cc.x, ya[20]);
            ya[5]  = ffma2(x0, cc.y, ya[5]);  ya[13] = ffma2(x1, cc.y, ya[13]); ya[21] = ffma2(x2, cc.y, ya[21]);
            ulonglong2 cd = crow[3];
            ya[6]  = ffma2(x0, cd.x, ya[6]);  ya[14] = ffma2(x1, cd.x, ya[14]); ya[22] = ffma2(x2, cd.x, ya[22]);
            ya[7]  = ffma2(x0, cd.y, ya[7]);  ya[15] = ffma2(x1, cd.y, ya[15]); ya[23] = ffma2(x2, cd.y, ya[23]);
        }
        #pragma unroll
        for (int u = 0; u < 4; u++) { c0[u] = n0[u]; c1[u] = n1[u]; c2[u] = n2[u]; }
    }
    #pragma unroll
    for (int pp = 0; pp < 3; pp++) {
        #pragma unroll
        for (int q = 0; q < 8; q++) {
            float2 f = unpack2(ya[pp * 8 + q]);
            g_yp[jc][((size_t)b * NC_ + 2 * q)     * P_ + pp * 256 + t] = f.x;
            g_yp[jc][((size_t)b * NC_ + 2 * q + 1) * P_ + pp * 256 + t] = f.y;
        }
    }
}

// ---------------- launch ----------------
extern "C" void kernel_launch(void* const* d_in, const int* in_sizes, int n_in,
                              void* d_out, int out_size) {
    const float* x = (const float*)d_in[0];
    const float* W = (const float*)d_in[1];
    if (n_in >= 2 && in_sizes[0] < in_sizes[1]) {
        const float* tmp = x; x = W; W = tmp;
    }
    float* out = (float*)d_out;
    (void)out_size;

    cudaFuncSetAttribute(k_routey, cudaFuncAttributeMaxDynamicSharedMemorySize,
                         RY_SMEM);

    dim3 gsq(16, 16);

    k_colsum<<<dim3(4, 64), 192>>>(x);
    k_s<0><<<gsq, 512>>>(W, nullptr);
    k_v<<<dim3(48, 16), 128>>>(W);

    // iteration 1
    k_routey<<<dim3(8, 64), 256, RY_SMEM>>>(x);
    k_s<1><<<gsq, 512>>>(W, nullptr);
    k_v<<<dim3(48, 16), 128>>>(W);

    // iteration 2 (final)
    k_routey<<<dim3(8, 64), 256, RY_SMEM>>>(x);
    k_s<1><<<gsq, 512>>>(W, out);
}

// round 13
// speedup vs baseline: 1.2651x; 1.1611x over previous
#include <cuda_runtime.h>

#define B_  64
#define J_  512
#define P_  768
#define NC_ 16
#define DC_ 64
#define WN_ 1024   // NC_*DC_

typedef unsigned long long ull;

// ---------------- scratch (device globals; no allocation allowed) ----------------
__device__ float  g_xbar[4][B_ * P_];       // colsum partials [jsplit][b*P+p]
__device__ float2 g_v2[B_][P_][16];         // v duplicated    [b][p][i]=(v,v)
__device__ float  g_yp[8][B_ * NC_ * P_];   // y partials      [jsplit][b][i][p]

// ---------------- packed f32x2 helpers ----------------
__device__ __forceinline__ ull ffma2(ull a, ull b, ull c) {
    ull d;
    asm("fma.rn.f32x2 %0, %1, %2, %3;" : "=l"(d) : "l"(a), "l"(b), "l"(c));
    return d;
}
__device__ __forceinline__ ull pack2(float v) {
    ull d; unsigned int u = __float_as_uint(v);
    asm("mov.b64 %0, {%1, %1};" : "=l"(d) : "r"(u));
    return d;
}
__device__ __forceinline__ float2 unpack2(ull u) {
    float2 f;
    f.x = __uint_as_float((unsigned int)u);
    f.y = __uint_as_float((unsigned int)(u >> 32));
    return f;
}

// ---------------- K1: xbar partials (float4, 16 lines in flight) --------------
__global__ void __launch_bounds__(192) k_colsum(const float* __restrict__ x) {
    int pq = threadIdx.x;
    int js = blockIdx.x;
    int b  = blockIdx.y;
    const float4* xp = (const float4*)(x + ((size_t)b * J_ + (size_t)js * 128) * P_) + pq;
    float4 a0 = make_float4(0.f, 0.f, 0.f, 0.f), a1 = a0, a2 = a0, a3 = a0;
    #pragma unroll 8
    for (int j = 0; j < 128; j += 4) {
        float4 v0 = xp[(size_t)(j + 0) * 192];
        float4 v1 = xp[(size_t)(j + 1) * 192];
        float4 v2 = xp[(size_t)(j + 2) * 192];
        float4 v3 = xp[(size_t)(j + 3) * 192];
        a0.x += v0.x; a0.y += v0.y; a0.z += v0.z; a0.w += v0.w;
        a1.x += v1.x; a1.y += v1.y; a1.z += v1.z; a1.w += v1.w;
        a2.x += v2.x; a2.y += v2.y; a2.z += v2.z; a2.w += v2.w;
        a3.x += v3.x; a3.y += v3.y; a3.z += v3.z; a3.w += v3.w;
    }
    float4 s;
    s.x = (a0.x + a1.x) + (a2.x + a3.x);
    s.y = (a0.y + a1.y) + (a2.y + a3.y);
    s.z = (a0.z + a1.z) + (a2.z + a3.z);
    s.w = (a0.w + a1.w) + (a2.w + a3.w);
    *(float4*)(g_xbar[js] + b * P_ + 4 * pq) = s;
}

// ---------------- K2: s = src@W_i, squash, fused v-projection -----------------
// grid (i=16, bg=16), block 512.
// Phase 1: GEMV + squash -> o in smem (os[4][64]) and optional `out`.
// Phase 2 (DO_V): v2[b][p][i] from L1-warm W slice.
template <int MODE, bool DO_V>
__global__ void __launch_bounds__(512) k_sv(const float* __restrict__ W,
                                            float* __restrict__ out) {
    int i  = blockIdx.x;
    int b0 = blockIdx.y * 4;
    __shared__ float  ys[4][P_];
    __shared__ float4 ss[4][4][16];
    __shared__ float  os[4][DC_];
    for (int idx = threadIdx.x; idx < 4 * (P_ / 4); idx += 512) {
        int bb = idx / (P_ / 4), pq = idx - bb * (P_ / 4);
        float4 s;
        if (MODE == 0) {
            size_t off = (size_t)(b0 + bb) * P_;
            float4 v0 = ((const float4*)(g_xbar[0] + off))[pq];
            float4 v1 = ((const float4*)(g_xbar[1] + off))[pq];
            float4 v2 = ((const float4*)(g_xbar[2] + off))[pq];
            float4 v3 = ((const float4*)(g_xbar[3] + off))[pq];
            s.x = (v0.x + v1.x) + (v2.x + v3.x);
            s.y = (v0.y + v1.y) + (v2.y + v3.y);
            s.z = (v0.z + v1.z) + (v2.z + v3.z);
            s.w = (v0.w + v1.w) + (v2.w + v3.w);
        } else {
            size_t off = ((size_t)(b0 + bb) * NC_ + i) * P_;
            s = make_float4(0.f, 0.f, 0.f, 0.f);
            #pragma unroll
            for (int sp = 0; sp < 8; sp++) {
                float4 v = ((const float4*)(g_yp[sp] + off))[pq];
                s.x += v.x; s.y += v.y; s.z += v.z; s.w += v.w;
            }
        }
        ((float4*)ys[bb])[pq] = s;
    }
    __syncthreads();

    int w = threadIdx.x >> 5, l = threadIdx.x & 31;
    int bb = w & 3, ph = w >> 2;                 // p-quarter of 192
    int qk = l & 15, pofs = l >> 4;
    const float* yrow  = ys[bb] + ph * 192;
    const float* wbase = W + ((size_t)(ph * 192)) * WN_ + i * DC_ + 4 * qk;

    float4 a[8];
    #pragma unroll
    for (int u = 0; u < 8; u++) a[u] = make_float4(0.f, 0.f, 0.f, 0.f);
    for (int p0 = 0; p0 < 192; p0 += 16) {
        #pragma unroll
        for (int u = 0; u < 8; u++) {
            int pr = p0 + 2 * u + pofs;
            float4 wv = *(const float4*)(wbase + (size_t)pr * WN_);
            float yv = yrow[pr];
            a[u].x += wv.x * yv; a[u].y += wv.y * yv;
            a[u].z += wv.z * yv; a[u].w += wv.w * yv;
        }
    }
    float4 acc;
    acc.x = ((a[0].x + a[1].x) + (a[2].x + a[3].x)) + ((a[4].x + a[5].x) + (a[6].x + a[7].x));
    acc.y = ((a[0].y + a[1].y) + (a[2].y + a[3].y)) + ((a[4].y + a[5].y) + (a[6].y + a[7].y));
    acc.z = ((a[0].z + a[1].z) + (a[2].z + a[3].z)) + ((a[4].z + a[5].z) + (a[6].z + a[7].z));
    acc.w = ((a[0].w + a[1].w) + (a[2].w + a[3].w)) + ((a[4].w + a[5].w) + (a[6].w + a[7].w));
    acc.x += __shfl_xor_sync(0xffffffffu, acc.x, 16);
    acc.y += __shfl_xor_sync(0xffffffffu, acc.y, 16);
    acc.z += __shfl_xor_sync(0xffffffffu, acc.z, 16);
    acc.w += __shfl_xor_sync(0xffffffffu, acc.w, 16);
    if (pofs == 0) ss[ph][bb][qk] = acc;
    __syncthreads();

    if (w < 4) {
        int qk2 = l >> 1, hi = l & 1;
        float2 s2 = make_float2(0.f, 0.f);
        #pragma unroll
        for (int p2 = 0; p2 < 4; p2++) {
            float4 v = ss[p2][w][qk2];
            s2.x += hi ? v.z : v.x;
            s2.y += hi ? v.w : v.y;
        }
        if (MODE == 0) { s2.x *= 0.0625f; s2.y *= 0.0625f; }
        float sq = s2.x * s2.x + s2.y * s2.y;
        #pragma unroll
        for (int s = 16; s > 0; s >>= 1) sq += __shfl_xor_sync(0xffffffffu, sq, s);
        float r = rsqrtf(sq + 1e-7f);
        s2.x *= r; s2.y *= r;
        ((float2*)os[w])[l] = s2;                       // lane l -> k {2l, 2l+1}
        if (out) *(float2*)(out + ((size_t)(b0 + w) * NC_ + i) * DC_ + 2 * l) = s2;
    }

    if (DO_V) {
        __syncthreads();
        // phase 2: warp w -> p rows [48w, 48w+48); lanes (pr=l>>2, kq=l&3).
        int pr = l >> 2, kq = l & 3;
        int pb = 48 * w;
        const float4* os4[4] = {(const float4*)os[0], (const float4*)os[1],
                                (const float4*)os[2], (const float4*)os[3]};
        #pragma unroll
        for (int sweep = 0; sweep < 6; sweep++) {
            int p = pb + 8 * sweep + pr;
            const float4* Wp = (const float4*)(W + (size_t)p * WN_ + i * DC_);
            float4 w0 = Wp[kq];
            float4 w1 = Wp[kq + 4];
            float4 w2 = Wp[kq + 8];
            float4 w3 = Wp[kq + 12];
            float part[4];
            #pragma unroll
            for (int b2 = 0; b2 < 4; b2++) {
                float4 o0 = os4[b2][kq];
                float4 o1 = os4[b2][kq + 4];
                float4 o2 = os4[b2][kq + 8];
                float4 o3 = os4[b2][kq + 12];
                part[b2] = (w0.x * o0.x + w0.y * o0.y + w0.z * o0.z + w0.w * o0.w)
                         + (w1.x * o1.x + w1.y * o1.y + w1.z * o1.z + w1.w * o1.w)
                         + (w2.x * o2.x + w2.y * o2.y + w2.z * o2.z + w2.w * o2.w)
                         + (w3.x * o3.x + w3.y * o3.y + w3.z * o3.z + w3.w * o3.w);
            }
            #pragma unroll
            for (int b2 = 0; b2 < 4; b2++) {
                part[b2] += __shfl_xor_sync(0xffffffffu, part[b2], 1);
                part[b2] += __shfl_xor_sync(0xffffffffu, part[b2], 2);
            }
            if (kq == 0) {
                #pragma unroll
                for (int b2 = 0; b2 < 4; b2++)
                    g_v2[b0 + b2][p][i] = make_float2(part[b2], part[b2]);
            }
        }
    }
}

// ---------------- K3: fused route (slab GEMM + softmax) + y partials ----------
// R12 config: full register prefetch + atomic-free merge + pipelined y phase.
#define RY_A    35072              // xs 32KB overlaid with pblw[8][64][17]
#define RY_VT   (128 * 16 * 8)     // 16384
#define RY_CS   (64 * 4 * 16)      //  4096
#define RY_SMEM (RY_A + RY_VT + RY_CS)

__global__ void __launch_bounds__(256, 2) k_routey(const float* __restrict__ x) {
    extern __shared__ char sm[];
    float*      xsf  = (float*)sm;                    // scalar view of xs units
    ulonglong2* xs16 = (ulonglong2*)sm;               // 16B-unit view
    float*      pblw = (float*)sm;                    // [8][64][17] overlay
    float2*     vt2  = (float2*)(sm + RY_A);          // [k][16]
    uint4*      vt2u = (uint4*)(sm + RY_A);
    float4*     cs   = (float4*)(sm + RY_A + RY_VT);  // [64][4]

    int b  = blockIdx.y;
    int jc = blockIdx.x;
    const float* xb = x + ((size_t)b * J_ + jc * 64) * P_;
    int t = threadIdx.x, w = t >> 5, l = t & 31;
    int tj = l & 7, ti = l >> 3;

    ull acc[16];
    #pragma unroll
    for (int q = 0; q < 16; q++) acc[q] = 0ull;

    const uint4* v2src = (const uint4*)&g_v2[b][0][0];   // 8 units per p-row

    // staging coordinates
    int sj[8], skq[8];
    #pragma unroll
    for (int q = 0; q < 8; q++) {
        int m = q * 8 + w;
        sj[q]  = (m & 15) * 4 + (l & 3);
        skq[q] = (m >> 4) * 8 + (l >> 2);
    }

    // prologue: FULL prefetch of slab 0 (x and v)
    float4 rx[8];
    uint4  rv[4];
    #pragma unroll
    for (int q = 0; q < 8; q++)
        rx[q] = ((const float4*)(xb + (size_t)sj[q] * P_))[skq[q]];
    #pragma unroll
    for (int q = 0; q < 4; q++)
        rv[q] = v2src[t + 256 * q];

    for (int s = 0; s < 6; s++) {
        __syncthreads();
        // xs transpose store (conflict-free via xor swizzle), pure STS
        #pragma unroll
        for (int q = 0; q < 8; q++) {
            int jq = sj[q] >> 2, jr = sj[q] & 3;
            int swz = jq ^ (skq[q] & 15);
            int base = (4 * skq[q]) * 16 + swz;
            xsf[(base + 0 * 16) * 4 + jr] = rx[q].x;
            xsf[(base + 1 * 16) * 4 + jr] = rx[q].y;
            xsf[(base + 2 * 16) * 4 + jr] = rx[q].z;
            xsf[(base + 3 * 16) * 4 + jr] = rx[q].w;
        }
        #pragma unroll
        for (int q = 0; q < 4; q++)
            vt2u[t + 256 * q] = rv[q];
        __syncthreads();
        // prefetch next slab during compute
        if (s < 5) {
            #pragma unroll
            for (int q = 0; q < 8; q++)
                rx[q] = ((const float4*)(xb + (size_t)sj[q] * P_ + 128 * (s + 1)))[skq[q]];
            #pragma unroll
            for (int q = 0; q < 4; q++)
                rv[q] = v2src[(size_t)(s + 1) * 1024 + t + 256 * q];
        }
        // compute: warp's k sub-range [16w, 16w+16)
        #pragma unroll
        for (int kk = 0; kk < 16; kk++) {
            int k = 16 * w + kk;
            int sw = (k >> 2) & 15;
            ulonglong2 xp0 = xs16[k * 16 + ((2 * tj)     ^ sw)];
            ulonglong2 xp1 = xs16[k * 16 + ((2 * tj + 1) ^ sw)];
            ulonglong2 v01 = *(const ulonglong2*)&vt2[k * 16 + 4 * ti];
            ulonglong2 v23 = *(const ulonglong2*)&vt2[k * 16 + 4 * ti + 2];
            acc[0]  = ffma2(xp0.x, v01.x, acc[0]);
            acc[1]  = ffma2(xp0.x, v01.y, acc[1]);
            acc[2]  = ffma2(xp0.x, v23.x, acc[2]);
            acc[3]  = ffma2(xp0.x, v23.y, acc[3]);
            acc[4]  = ffma2(xp0.y, v01.x, acc[4]);
            acc[5]  = ffma2(xp0.y, v01.y, acc[5]);
            acc[6]  = ffma2(xp0.y, v23.x, acc[6]);
            acc[7]  = ffma2(xp0.y, v23.y, acc[7]);
            acc[8]  = ffma2(xp1.x, v01.x, acc[8]);
            acc[9]  = ffma2(xp1.x, v01.y, acc[9]);
            acc[10] = ffma2(xp1.x, v23.x, acc[10]);
            acc[11] = ffma2(xp1.x, v23.y, acc[11]);
            acc[12] = ffma2(xp1.y, v01.x, acc[12]);
            acc[13] = ffma2(xp1.y, v01.y, acc[13]);
            acc[14] = ffma2(xp1.y, v23.x, acc[14]);
            acc[15] = ffma2(xp1.y, v23.y, acc[15]);
        }
    }
    __syncthreads();   // xs dead; region A becomes pblw
    // per-warp partial logits (plain STS, no atomics)
    #pragma unroll
    for (int jp = 0; jp < 4; jp++) {
        int j0 = 8 * tj + 2 * jp;
        #pragma unroll
        for (int ii = 0; ii < 4; ii++) {
            float2 f = unpack2(acc[4 * jp + ii]);
            pblw[w * 1088 + j0 * 17 + 4 * ti + ii]       = f.x;
            pblw[w * 1088 + (j0 + 1) * 17 + 4 * ti + ii] = f.y;
        }
    }
    __syncthreads();
    if (t < 64) {
        float bl[16];
        #pragma unroll
        for (int q = 0; q < 16; q++) {
            float s = 0.f;
            #pragma unroll
            for (int ww = 0; ww < 8; ww++) s += pblw[ww * 1088 + t * 17 + q];
            bl[q] = s;
        }
        float m = bl[0];
        #pragma unroll
        for (int q = 1; q < 16; q++) m = fmaxf(m, bl[q]);
        float sum = 0.f;
        #pragma unroll
        for (int q = 0; q < 16; q++) { bl[q] = __expf(bl[q] - m); sum += bl[q]; }
        float inv = 1.0f / sum;
        #pragma unroll
        for (int q = 0; q < 4; q++)
            cs[t * 4 + q] = make_float4(bl[4 * q] * inv, bl[4 * q + 1] * inv,
                                        bl[4 * q + 2] * inv, bl[4 * q + 3] * inv);
    }
    __syncthreads();

    // ---- y phase: software-pipelined (batch 4 j, prefetch next batch) ----
    ull ya[24];
    #pragma unroll
    for (int q = 0; q < 24; q++) ya[q] = 0ull;

    float c0[4], c1[4], c2[4];
    #pragma unroll
    for (int u = 0; u < 4; u++) {
        const float* xr = xb + (size_t)u * P_;
        c0[u] = xr[t]; c1[u] = xr[t + 256]; c2[u] = xr[t + 512];
    }
    for (int jb = 0; jb < 64; jb += 4) {
        float n0[4], n1[4], n2[4];
        if (jb < 60) {
            #pragma unroll
            for (int u = 0; u < 4; u++) {
                const float* xn = xb + (size_t)(jb + 4 + u) * P_;
                n0[u] = xn[t]; n1[u] = xn[t + 256]; n2[u] = xn[t + 512];
            }
        } else {
            #pragma unroll
            for (int u = 0; u < 4; u++) { n0[u] = 0.f; n1[u] = 0.f; n2[u] = 0.f; }
        }
        #pragma unroll
        for (int u = 0; u < 4; u++) {
            int j = jb + u;
            ull x0 = pack2(c0[u]), x1 = pack2(c1[u]), x2 = pack2(c2[u]);
            const ulonglong2* crow = (const ulonglong2*)(cs + j * 4);
            ulonglong2 ca = crow[0];
            ya[0]  = ffma2(x0, ca.x, ya[0]);  ya[8]  = ffma2(x1, ca.x, ya[8]);  ya[16] = ffma2(x2, ca.x, ya[16]);
            ya[1]  = ffma2(x0, ca.y, ya[1]);  ya[9]  = ffma2(x1, ca.y, ya[9]);  ya[17] = ffma2(x2, ca.y, ya[17]);
            ulonglong2 cb2 = crow[1];
            ya[2]  = ffma2(x0, cb2.x, ya[2]); ya[10] = ffma2(x1, cb2.x, ya[10]); ya[18] = ffma2(x2, cb2.x, ya[18]);
            ya[3]  = ffma2(x0, cb2.y, ya[3]); ya[11] = ffma2(x1, cb2.y, ya[11]); ya[19] = ffma2(x2, cb2.y, ya[19]);
            ulonglong2 cc = crow[2];
            ya[4]  = ffma2(x0, cc.x, ya[4]);  ya[12] = ffma2(x1, cc.x, ya[12]); ya[20] = ffma2(x2, cc.x, ya[20]);
            ya[5]  = ffma2(x0, cc.y, ya[5]);  ya[13] = ffma2(x1, cc.y, ya[13]); ya[21] = ffma2(x2, cc.y, ya[21]);
            ulonglong2 cd = crow[3];
            ya[6]  = ffma2(x0, cd.x, ya[6]);  ya[14] = ffma2(x1, cd.x, ya[14]); ya[22] = ffma2(x2, cd.x, ya[22]);
            ya[7]  = ffma2(x0, cd.y, ya[7]);  ya[15] = ffma2(x1, cd.y, ya[15]); ya[23] = ffma2(x2, cd.y, ya[23]);
        }
        #pragma unroll
        for (int u = 0; u < 4; u++) { c0[u] = n0[u]; c1[u] = n1[u]; c2[u] = n2[u]; }
    }
    #pragma unroll
    for (int pp = 0; pp < 3; pp++) {
        #pragma unroll
        for (int q = 0; q < 8; q++) {
            float2 f = unpack2(ya[pp * 8 + q]);
            g_yp[jc][((size_t)b * NC_ + 2 * q)     * P_ + pp * 256 + t] = f.x;
            g_yp[jc][((size_t)b * NC_ + 2 * q + 1) * P_ + pp * 256 + t] = f.y;
        }
    }
}

// ---------------- launch ----------------
extern "C" void kernel_launch(void* const* d_in, const int* in_sizes, int n_in,
                              void* d_out, int out_size) {
    const float* x = (const float*)d_in[0];
    const float* W = (const float*)d_in[1];
    if (n_in >= 2 && in_sizes[0] < in_sizes[1]) {
        const float* tmp = x; x = W; W = tmp;
    }
    float* out = (float*)d_out;
    (void)out_size;

    cudaFuncSetAttribute(k_routey, cudaFuncAttributeMaxDynamicSharedMemorySize,
                         RY_SMEM);

    dim3 gsq(16, 16);

    k_colsum<<<dim3(4, 64), 192>>>(x);
    k_sv<0, true><<<gsq, 512>>>(W, nullptr);

    // iteration 1
    k_routey<<<dim3(8, 64), 256, RY_SMEM>>>(x);
    k_sv<1, true><<<gsq, 512>>>(W, nullptr);

    // iteration 2 (final)
    k_routey<<<dim3(8, 64), 256, RY_SMEM>>>(x);
    k_sv<1, false><<<gsq, 512>>>(W, out);
}